// round 1
// baseline (speedup 1.0000x reference)
#include <cuda_runtime.h>
#include <cuda_bf16.h>
#include <math.h>

// Problem constants
#define BATCH 8
#define T_SEQ 1024
#define C_EMB 768
#define NH    8
#define HD    96          // head dim
#define M_ROWS (BATCH * T_SEQ)   // 8192

// ---------------------------------------------------------------------------
// Scratch (device globals: allocation inside kernel_launch is forbidden)
// ---------------------------------------------------------------------------
__device__ float g_qkv[(size_t)M_ROWS * 3 * C_EMB];   // (B*T, 3C) = 75.5 MB
__device__ float g_att[(size_t)M_ROWS * C_EMB];       // (B*T, C)  = 25 MB

// ---------------------------------------------------------------------------
// SGEMM:  C[m][n] = sum_k A[m][k] * W[n][k] + bias[n]
// A: MxK row-major, W: NxK row-major (both K-contiguous -> float4 loads)
// Tiles: 128x128x8, 256 threads, 8x8 per-thread register tile.
// M % 128 == 0, N % 128 == 0, K % 8 == 0 guaranteed by caller.
// ---------------------------------------------------------------------------
__global__ __launch_bounds__(256) void sgemm_nt_bias(
    const float* __restrict__ A, const float* __restrict__ W,
    const float* __restrict__ bias, float* __restrict__ C,
    int M, int N, int K)
{
    constexpr int BM = 128, BN = 128, BK = 8;
    __shared__ float As[BK][BM];
    __shared__ float Bs[BK][BN];

    const int tid = threadIdx.x;
    const int bm = blockIdx.y * BM;
    const int bn = blockIdx.x * BN;
    const int tr = tid / 16;       // 0..15
    const int tc = tid % 16;       // 0..15

    const int lr = tid >> 1;             // 0..127
    const int lc = (tid & 1) * 4;        // 0 or 4

    const float* Ap = A + (size_t)(bm + lr) * K + lc;
    const float* Wp = W + (size_t)(bn + lr) * K + lc;

    float acc[8][8];
#pragma unroll
    for (int i = 0; i < 8; i++)
#pragma unroll
        for (int j = 0; j < 8; j++) acc[i][j] = 0.f;

    for (int k0 = 0; k0 < K; k0 += BK) {
        float4 av = *(const float4*)(Ap + k0);
        float4 wv = *(const float4*)(Wp + k0);
        As[lc + 0][lr] = av.x; As[lc + 1][lr] = av.y;
        As[lc + 2][lr] = av.z; As[lc + 3][lr] = av.w;
        Bs[lc + 0][lr] = wv.x; Bs[lc + 1][lr] = wv.y;
        Bs[lc + 2][lr] = wv.z; Bs[lc + 3][lr] = wv.w;
        __syncthreads();

#pragma unroll
        for (int kk = 0; kk < BK; kk++) {
            float ra[8], rb[8];
#pragma unroll
            for (int i = 0; i < 8; i++) ra[i] = As[kk][tr * 8 + i];
#pragma unroll
            for (int j = 0; j < 8; j++) rb[j] = Bs[kk][tc * 8 + j];
#pragma unroll
            for (int i = 0; i < 8; i++)
#pragma unroll
                for (int j = 0; j < 8; j++) acc[i][j] += ra[i] * rb[j];
        }
        __syncthreads();
    }

    float bj[8];
#pragma unroll
    for (int j = 0; j < 8; j++) bj[j] = bias[bn + tc * 8 + j];

#pragma unroll
    for (int i = 0; i < 8; i++) {
        float* cp = C + (size_t)(bm + tr * 8 + i) * N + bn + tc * 8;
        float4 v0, v1;
        v0.x = acc[i][0] + bj[0]; v0.y = acc[i][1] + bj[1];
        v0.z = acc[i][2] + bj[2]; v0.w = acc[i][3] + bj[3];
        v1.x = acc[i][4] + bj[4]; v1.y = acc[i][5] + bj[5];
        v1.z = acc[i][6] + bj[6]; v1.w = acc[i][7] + bj[7];
        *(float4*)(cp + 0) = v0;
        *(float4*)(cp + 4) = v1;
    }
}

// ---------------------------------------------------------------------------
// Flash attention (causal, online softmax).
// qkv layout: (B*T, 3C); q at col h*96, k at col C+h*96, v at col 2C+h*96.
// One block per (q-tile of 64, head, batch); 256 threads.
// Thread map: q = tid>>2 (0..63), sub = tid&3. Thread owns S[q][sub+4j], j<16
// and O[q][sub*24 .. sub*24+23].
// smem strides chosen for conflict-free float4 access:
//   Qs/Ks stride 100 (bank = 4*row + col), Ss stride 68.
// ---------------------------------------------------------------------------
#define QS_STRIDE 100
#define KS_STRIDE 100
#define SS_STRIDE 68
#define FLASH_SMEM_FLOATS (64 * QS_STRIDE + 64 * KS_STRIDE + 64 * HD + 64 * SS_STRIDE)
#define FLASH_SMEM_BYTES (FLASH_SMEM_FLOATS * 4)

__global__ __launch_bounds__(256) void flash_attn(
    const float* __restrict__ qkv, float* __restrict__ out)
{
    extern __shared__ float sm[];
    float* Qs = sm;                       // 64 * 100
    float* Ks = Qs + 64 * QS_STRIDE;      // 64 * 100
    float* Vs = Ks + 64 * KS_STRIDE;      // 64 * 96
    float* Ss = Vs + 64 * HD;             // 64 * 68

    const int qt = blockIdx.x;  // q-tile (16)
    const int h  = blockIdx.y;  // head (8)
    const int b  = blockIdx.z;  // batch (8)
    const int tid = threadIdx.x;
    const int q   = tid >> 2;
    const int sub = tid & 3;

    const float rscale = 0.1020620726159658f;  // 1/sqrt(96)

    // Load + scale Q tile (stays for whole block)
    const float* qbase = qkv + (size_t)(b * T_SEQ + qt * 64) * 3 * C_EMB + h * HD;
    for (int i = tid; i < 64 * HD; i += 256) {
        int r = i / HD, c = i % HD;
        Qs[r * QS_STRIDE + c] = qbase[(size_t)r * 3 * C_EMB + c] * rscale;
    }

    float4 o4[6];
#pragma unroll
    for (int d = 0; d < 6; d++) o4[d] = make_float4(0.f, 0.f, 0.f, 0.f);
    float m = -1e30f, l = 0.f;

    for (int kt = 0; kt <= qt; kt++) {
        __syncthreads();   // previous-iter smem reads complete
        const float* kbase = qkv + (size_t)(b * T_SEQ + kt * 64) * 3 * C_EMB + C_EMB + h * HD;
        const float* vbase = kbase + C_EMB;
        for (int i = tid; i < 64 * HD; i += 256) {
            int r = i / HD, c = i % HD;
            float kvv = kbase[(size_t)r * 3 * C_EMB + c];
            float vvv = vbase[(size_t)r * 3 * C_EMB + c];
            Ks[r * KS_STRIDE + c] = kvv;
            Vs[r * HD + c] = vvv;
        }
        __syncthreads();

        // ---- S = Q K^T (thread: 1 q row x 16 k cols, k = sub + 4j) ----
        float s[16];
#pragma unroll
        for (int j = 0; j < 16; j++) s[j] = 0.f;
        for (int kk = 0; kk < HD; kk += 4) {
            float4 qv = *(const float4*)&Qs[q * QS_STRIDE + kk];
#pragma unroll
            for (int j = 0; j < 16; j++) {
                float4 kv = *(const float4*)&Ks[(sub + 4 * j) * KS_STRIDE + kk];
                s[j] += qv.x * kv.x + qv.y * kv.y + qv.z * kv.z + qv.w * kv.w;
            }
        }
        if (kt == qt) {
#pragma unroll
            for (int j = 0; j < 16; j++)
                if (sub + 4 * j > q) s[j] = -1e30f;
        }

        // ---- online softmax ----
        float mx = s[0];
#pragma unroll
        for (int j = 1; j < 16; j++) mx = fmaxf(mx, s[j]);
        mx = fmaxf(mx, __shfl_xor_sync(0xffffffffu, mx, 1));
        mx = fmaxf(mx, __shfl_xor_sync(0xffffffffu, mx, 2));
        float m_new = fmaxf(m, mx);
        float corr = __expf(m - m_new);
        float rs = 0.f;
#pragma unroll
        for (int j = 0; j < 16; j++) {
            float p = __expf(s[j] - m_new);
            Ss[q * SS_STRIDE + sub + 4 * j] = p;
            rs += p;
        }
        rs += __shfl_xor_sync(0xffffffffu, rs, 1);
        rs += __shfl_xor_sync(0xffffffffu, rs, 2);
        l = l * corr + rs;
        m = m_new;
#pragma unroll
        for (int d = 0; d < 6; d++) {
            o4[d].x *= corr; o4[d].y *= corr; o4[d].z *= corr; o4[d].w *= corr;
        }
        __syncthreads();   // Ss visible to all

        // ---- O += P V (thread: 1 q row x 24 d cols at sub*24) ----
#pragma unroll 4
        for (int k = 0; k < 64; k++) {
            float p = Ss[q * SS_STRIDE + k];
            const float4* vp = (const float4*)&Vs[k * HD + sub * 24];
#pragma unroll
            for (int d = 0; d < 6; d++) {
                float4 v = vp[d];
                o4[d].x += p * v.x; o4[d].y += p * v.y;
                o4[d].z += p * v.z; o4[d].w += p * v.w;
            }
        }
    }

    const float inv_l = 1.f / l;
    float* ob = out + (size_t)(b * T_SEQ + qt * 64 + q) * C_EMB + h * HD + sub * 24;
#pragma unroll
    for (int d = 0; d < 6; d++) {
        float4 v;
        v.x = o4[d].x * inv_l; v.y = o4[d].y * inv_l;
        v.z = o4[d].z * inv_l; v.w = o4[d].w * inv_l;
        *(float4*)(ob + 4 * d) = v;
    }
}

// ---------------------------------------------------------------------------
// Launch
// ---------------------------------------------------------------------------
extern "C" void kernel_launch(void* const* d_in, const int* in_sizes, int n_in,
                              void* d_out, int out_size)
{
    (void)in_sizes; (void)n_in; (void)out_size;
    const float* x  = (const float*)d_in[0];   // (8,1024,768)
    const float* w1 = (const float*)d_in[1];   // (2304,768)
    const float* b1 = (const float*)d_in[2];   // (2304,)
    const float* w2 = (const float*)d_in[3];   // (768,768)
    const float* b2 = (const float*)d_in[4];   // (768,)
    // d_in[5] is the tril mask; causality is hardcoded.
    float* out = (float*)d_out;

    float *qkv = nullptr, *att = nullptr;
    cudaGetSymbolAddress((void**)&qkv, g_qkv);
    cudaGetSymbolAddress((void**)&att, g_att);

    cudaFuncSetAttribute(flash_attn,
                         cudaFuncAttributeMaxDynamicSharedMemorySize,
                         FLASH_SMEM_BYTES);

    // QKV projection: (8192 x 2304 x 768)
    sgemm_nt_bias<<<dim3(3 * C_EMB / 128, M_ROWS / 128), 256>>>(
        x, w1, b1, qkv, M_ROWS, 3 * C_EMB, C_EMB);

    // Causal attention
    flash_attn<<<dim3(T_SEQ / 64, NH, BATCH), 256, FLASH_SMEM_BYTES>>>(qkv, att);

    // Output projection: (8192 x 768 x 768)
    sgemm_nt_bias<<<dim3(C_EMB / 128, M_ROWS / 128), 256>>>(
        att, w2, b2, out, M_ROWS, C_EMB, C_EMB);
}

// round 2
// speedup vs baseline: 1.4311x; 1.4311x over previous
#include <cuda_runtime.h>
#include <cuda_bf16.h>
#include <math.h>

// Problem constants
#define BATCH 8
#define T_SEQ 1024
#define C_EMB 768
#define NH    8
#define HD    96
#define M_ROWS (BATCH * T_SEQ)   // 8192

// ---------------------------------------------------------------------------
// Scratch (device globals: allocation inside kernel_launch is forbidden)
// ---------------------------------------------------------------------------
__device__ float g_qkv[(size_t)M_ROWS * 3 * C_EMB];   // (B*T, 3C)
__device__ float g_att[(size_t)M_ROWS * C_EMB];       // (B*T, C)

// ---------------------------------------------------------------------------
// SGEMM:  C[m][n] = sum_k A[m][k] * W[n][k] + bias[n]
// A: MxK row-major, W: NxK row-major.
// 128x128x16 tiles, 256 threads, 8x8 register tile, double-buffered smem,
// float4 shared loads. K % 16 == 0, M,N % 128 == 0.
// ---------------------------------------------------------------------------
__global__ __launch_bounds__(256, 2) void sgemm_nt_bias(
    const float* __restrict__ A, const float* __restrict__ W,
    const float* __restrict__ bias, float* __restrict__ C,
    int M, int N, int K)
{
    __shared__ float As[2][16][128];
    __shared__ float Bs[2][16][128];

    const int tid = threadIdx.x;
    const int bm = blockIdx.y * 128;
    const int bn = blockIdx.x * 128;
    const int tr = tid >> 4;     // 0..15
    const int tc = tid & 15;     // 0..15

    // loader: thread handles float4 slots f = tid and tid+256 (rows +64)
    const int lr = tid >> 2;             // 0..63
    const int lc = (tid & 3) * 4;        // 0,4,8,12

    const float* Ap0 = A + (size_t)(bm + lr) * K + lc;
    const float* Ap1 = A + (size_t)(bm + 64 + lr) * K + lc;
    const float* Wp0 = W + (size_t)(bn + lr) * K + lc;
    const float* Wp1 = W + (size_t)(bn + 64 + lr) * K + lc;

    float acc[8][8];
#pragma unroll
    for (int i = 0; i < 8; i++)
#pragma unroll
        for (int j = 0; j < 8; j++) acc[i][j] = 0.f;

    // preload tile 0
    {
        float4 a0 = *(const float4*)(Ap0);
        float4 a1 = *(const float4*)(Ap1);
        float4 b0 = *(const float4*)(Wp0);
        float4 b1 = *(const float4*)(Wp1);
        As[0][lc + 0][lr] = a0.x; As[0][lc + 1][lr] = a0.y;
        As[0][lc + 2][lr] = a0.z; As[0][lc + 3][lr] = a0.w;
        As[0][lc + 0][lr + 64] = a1.x; As[0][lc + 1][lr + 64] = a1.y;
        As[0][lc + 2][lr + 64] = a1.z; As[0][lc + 3][lr + 64] = a1.w;
        Bs[0][lc + 0][lr] = b0.x; Bs[0][lc + 1][lr] = b0.y;
        Bs[0][lc + 2][lr] = b0.z; Bs[0][lc + 3][lr] = b0.w;
        Bs[0][lc + 0][lr + 64] = b1.x; Bs[0][lc + 1][lr + 64] = b1.y;
        Bs[0][lc + 2][lr + 64] = b1.z; Bs[0][lc + 3][lr + 64] = b1.w;
    }
    __syncthreads();

    const int nt = K >> 4;
    int buf = 0;
    for (int t = 0; t < nt; t++) {
        float4 a0n, a1n, b0n, b1n;
        const bool more = (t + 1) < nt;
        if (more) {
            int ko = (t + 1) << 4;
            a0n = *(const float4*)(Ap0 + ko);
            a1n = *(const float4*)(Ap1 + ko);
            b0n = *(const float4*)(Wp0 + ko);
            b1n = *(const float4*)(Wp1 + ko);
        }

#pragma unroll
        for (int kk = 0; kk < 16; kk++) {
            float4 x0 = *(const float4*)&As[buf][kk][tr * 8];
            float4 x1 = *(const float4*)&As[buf][kk][tr * 8 + 4];
            float4 y0 = *(const float4*)&Bs[buf][kk][tc * 8];
            float4 y1 = *(const float4*)&Bs[buf][kk][tc * 8 + 4];
            float ra[8] = {x0.x, x0.y, x0.z, x0.w, x1.x, x1.y, x1.z, x1.w};
            float rb[8] = {y0.x, y0.y, y0.z, y0.w, y1.x, y1.y, y1.z, y1.w};
#pragma unroll
            for (int i = 0; i < 8; i++)
#pragma unroll
                for (int j = 0; j < 8; j++) acc[i][j] += ra[i] * rb[j];
        }

        if (more) {
            int nb = buf ^ 1;
            As[nb][lc + 0][lr] = a0n.x; As[nb][lc + 1][lr] = a0n.y;
            As[nb][lc + 2][lr] = a0n.z; As[nb][lc + 3][lr] = a0n.w;
            As[nb][lc + 0][lr + 64] = a1n.x; As[nb][lc + 1][lr + 64] = a1n.y;
            As[nb][lc + 2][lr + 64] = a1n.z; As[nb][lc + 3][lr + 64] = a1n.w;
            Bs[nb][lc + 0][lr] = b0n.x; Bs[nb][lc + 1][lr] = b0n.y;
            Bs[nb][lc + 2][lr] = b0n.z; Bs[nb][lc + 3][lr] = b0n.w;
            Bs[nb][lc + 0][lr + 64] = b1n.x; Bs[nb][lc + 1][lr + 64] = b1n.y;
            Bs[nb][lc + 2][lr + 64] = b1n.z; Bs[nb][lc + 3][lr + 64] = b1n.w;
        }
        __syncthreads();
        buf ^= 1;
    }

    float bj[8];
#pragma unroll
    for (int j = 0; j < 8; j++) bj[j] = bias[bn + tc * 8 + j];

#pragma unroll
    for (int i = 0; i < 8; i++) {
        float* cp = C + (size_t)(bm + tr * 8 + i) * N + bn + tc * 8;
        float4 v0, v1;
        v0.x = acc[i][0] + bj[0]; v0.y = acc[i][1] + bj[1];
        v0.z = acc[i][2] + bj[2]; v0.w = acc[i][3] + bj[3];
        v1.x = acc[i][4] + bj[4]; v1.y = acc[i][5] + bj[5];
        v1.z = acc[i][6] + bj[6]; v1.w = acc[i][7] + bj[7];
        *(float4*)(cp + 0) = v0;
        *(float4*)(cp + 4) = v1;
    }
}

// ---------------------------------------------------------------------------
// Flash attention (causal, online softmax), FFMA-bound layout.
// 128 threads/block, block = (q-tile 64, head, batch).
// Thread tile: 4 q-rows x 8 k-cols (QK) and 4 q-rows x 12 d-cols (PV).
// tq = tid>>3 (0..15), tk = tid&7 (0..7): softmax reductions warp-local.
// Transposed smem: Qt[d][q], Kt[d][k], Pt[k][q]; V row-major [k][d].
// ---------------------------------------------------------------------------
#define QT_STRIDE 68
#define KT_STRIDE 68
#define VS_STRIDE 96
#define PT_STRIDE 68
#define FLASH_SMEM_FLOATS (96*QT_STRIDE + 96*KT_STRIDE + 64*VS_STRIDE + 64*PT_STRIDE)
#define FLASH_SMEM_BYTES  (FLASH_SMEM_FLOATS * 4)

__global__ __launch_bounds__(128) void flash_attn(
    const float* __restrict__ qkv, float* __restrict__ out)
{
    extern __shared__ float sm[];
    float* Qt = sm;                        // [96][QT_STRIDE]
    float* Kt = Qt + 96 * QT_STRIDE;       // [96][KT_STRIDE]
    float* Vs = Kt + 96 * KT_STRIDE;       // [64][VS_STRIDE]
    float* Pt = Vs + 64 * VS_STRIDE;       // [64][PT_STRIDE]

    const int qt = 15 - (int)blockIdx.x;   // heavy tiles first
    const int h  = blockIdx.y;
    const int b  = blockIdx.z;
    const int tid = threadIdx.x;
    const int tq = tid >> 3;   // 0..15 -> q rows 4tq..4tq+3
    const int tk = tid & 7;    // 0..7  -> k cols 8tk..8tk+7, d cols 12tk..+11

    const float rscale = 0.10206207261596577f;  // 1/sqrt(96)

    // Load + scale Q, store transposed Qt[d][q]
    const float* qbase = qkv + (size_t)(b * T_SEQ + qt * 64) * 3 * C_EMB + h * HD;
    for (int i = tid; i < 64 * 24; i += 128) {
        int r = i / 24, c4 = (i % 24) * 4;
        float4 v = *(const float4*)(qbase + (size_t)r * 3 * C_EMB + c4);
        Qt[(c4 + 0) * QT_STRIDE + r] = v.x * rscale;
        Qt[(c4 + 1) * QT_STRIDE + r] = v.y * rscale;
        Qt[(c4 + 2) * QT_STRIDE + r] = v.z * rscale;
        Qt[(c4 + 3) * QT_STRIDE + r] = v.w * rscale;
    }

    float o[4][12];
#pragma unroll
    for (int i = 0; i < 4; i++)
#pragma unroll
        for (int d = 0; d < 12; d++) o[i][d] = 0.f;
    float m[4] = {-1e30f, -1e30f, -1e30f, -1e30f};
    float l[4] = {0.f, 0.f, 0.f, 0.f};

    for (int kt = 0; kt <= qt; kt++) {
        __syncthreads();   // previous iteration's smem reads complete
        const float* kbase = qkv + (size_t)(b * T_SEQ + kt * 64) * 3 * C_EMB + C_EMB + h * HD;
        const float* vbase = kbase + C_EMB;
        for (int i = tid; i < 64 * 24; i += 128) {
            int r = i / 24, c4 = (i % 24) * 4;
            float4 kv = *(const float4*)(kbase + (size_t)r * 3 * C_EMB + c4);
            float4 vv = *(const float4*)(vbase + (size_t)r * 3 * C_EMB + c4);
            Kt[(c4 + 0) * KT_STRIDE + r] = kv.x;
            Kt[(c4 + 1) * KT_STRIDE + r] = kv.y;
            Kt[(c4 + 2) * KT_STRIDE + r] = kv.z;
            Kt[(c4 + 3) * KT_STRIDE + r] = kv.w;
            *(float4*)&Vs[r * VS_STRIDE + c4] = vv;
        }
        __syncthreads();

        // ---- S = Q K^T : 4q x 8k per thread ----
        float s[4][8];
#pragma unroll
        for (int i = 0; i < 4; i++)
#pragma unroll
            for (int j = 0; j < 8; j++) s[i][j] = 0.f;

#pragma unroll 8
        for (int kk = 0; kk < HD; kk++) {
            float4 qv = *(const float4*)&Qt[kk * QT_STRIDE + 4 * tq];
            float4 k0 = *(const float4*)&Kt[kk * KT_STRIDE + 8 * tk];
            float4 k1 = *(const float4*)&Kt[kk * KT_STRIDE + 8 * tk + 4];
            float qa[4] = {qv.x, qv.y, qv.z, qv.w};
            float kb[8] = {k0.x, k0.y, k0.z, k0.w, k1.x, k1.y, k1.z, k1.w};
#pragma unroll
            for (int i = 0; i < 4; i++)
#pragma unroll
                for (int j = 0; j < 8; j++) s[i][j] += qa[i] * kb[j];
        }

        if (kt == qt) {
#pragma unroll
            for (int i = 0; i < 4; i++)
#pragma unroll
                for (int j = 0; j < 8; j++)
                    if (8 * tk + j > 4 * tq + i) s[i][j] = -1e30f;
        }

        // ---- online softmax (row reductions across tk lanes: same warp) ----
        float corr[4];
#pragma unroll
        for (int i = 0; i < 4; i++) {
            float mx = s[i][0];
#pragma unroll
            for (int j = 1; j < 8; j++) mx = fmaxf(mx, s[i][j]);
            mx = fmaxf(mx, __shfl_xor_sync(0xffffffffu, mx, 1));
            mx = fmaxf(mx, __shfl_xor_sync(0xffffffffu, mx, 2));
            mx = fmaxf(mx, __shfl_xor_sync(0xffffffffu, mx, 4));
            float mn = fmaxf(m[i], mx);
            corr[i] = __expf(m[i] - mn);
            m[i] = mn;
        }
        float rs[4];
#pragma unroll
        for (int i = 0; i < 4; i++) {
            rs[i] = 0.f;
#pragma unroll
            for (int j = 0; j < 8; j++) {
                s[i][j] = __expf(s[i][j] - m[i]);
                rs[i] += s[i][j];
            }
        }
        // store P transposed: Pt[k][q]
#pragma unroll
        for (int j = 0; j < 8; j++) {
            float4 p;
            p.x = s[0][j]; p.y = s[1][j]; p.z = s[2][j]; p.w = s[3][j];
            *(float4*)&Pt[(8 * tk + j) * PT_STRIDE + 4 * tq] = p;
        }
#pragma unroll
        for (int i = 0; i < 4; i++) {
            rs[i] += __shfl_xor_sync(0xffffffffu, rs[i], 1);
            rs[i] += __shfl_xor_sync(0xffffffffu, rs[i], 2);
            rs[i] += __shfl_xor_sync(0xffffffffu, rs[i], 4);
            l[i] = l[i] * corr[i] + rs[i];
#pragma unroll
            for (int d = 0; d < 12; d++) o[i][d] *= corr[i];
        }
        __syncthreads();   // Pt visible

        // ---- O += P V : 4q x 12d per thread ----
#pragma unroll 4
        for (int k = 0; k < 64; k++) {
            float4 p = *(const float4*)&Pt[k * PT_STRIDE + 4 * tq];
            float pa[4] = {p.x, p.y, p.z, p.w};
            float4 v0 = *(const float4*)&Vs[k * VS_STRIDE + 12 * tk];
            float4 v1 = *(const float4*)&Vs[k * VS_STRIDE + 12 * tk + 4];
            float4 v2 = *(const float4*)&Vs[k * VS_STRIDE + 12 * tk + 8];
            float vb[12] = {v0.x, v0.y, v0.z, v0.w,
                            v1.x, v1.y, v1.z, v1.w,
                            v2.x, v2.y, v2.z, v2.w};
#pragma unroll
            for (int i = 0; i < 4; i++)
#pragma unroll
                for (int d = 0; d < 12; d++) o[i][d] += pa[i] * vb[d];
        }
    }

#pragma unroll
    for (int i = 0; i < 4; i++) {
        float inv_l = 1.f / l[i];
        float* ob = out + (size_t)(b * T_SEQ + qt * 64 + 4 * tq + i) * C_EMB
                        + h * HD + 12 * tk;
        float4 w0, w1, w2;
        w0.x = o[i][0] * inv_l;  w0.y = o[i][1] * inv_l;
        w0.z = o[i][2] * inv_l;  w0.w = o[i][3] * inv_l;
        w1.x = o[i][4] * inv_l;  w1.y = o[i][5] * inv_l;
        w1.z = o[i][6] * inv_l;  w1.w = o[i][7] * inv_l;
        w2.x = o[i][8] * inv_l;  w2.y = o[i][9] * inv_l;
        w2.z = o[i][10] * inv_l; w2.w = o[i][11] * inv_l;
        *(float4*)(ob + 0) = w0;
        *(float4*)(ob + 4) = w1;
        *(float4*)(ob + 8) = w2;
    }
}

// ---------------------------------------------------------------------------
// Launch
// ---------------------------------------------------------------------------
extern "C" void kernel_launch(void* const* d_in, const int* in_sizes, int n_in,
                              void* d_out, int out_size)
{
    (void)in_sizes; (void)n_in; (void)out_size;
    const float* x  = (const float*)d_in[0];   // (8,1024,768)
    const float* w1 = (const float*)d_in[1];   // (2304,768)
    const float* b1 = (const float*)d_in[2];   // (2304,)
    const float* w2 = (const float*)d_in[3];   // (768,768)
    const float* b2 = (const float*)d_in[4];   // (768,)
    float* out = (float*)d_out;

    float *qkv = nullptr, *att = nullptr;
    cudaGetSymbolAddress((void**)&qkv, g_qkv);
    cudaGetSymbolAddress((void**)&att, g_att);

    cudaFuncSetAttribute(flash_attn,
                         cudaFuncAttributeMaxDynamicSharedMemorySize,
                         FLASH_SMEM_BYTES);

    // QKV projection: 8192 x 2304 x 768
    sgemm_nt_bias<<<dim3(3 * C_EMB / 128, M_ROWS / 128), 256>>>(
        x, w1, b1, qkv, M_ROWS, 3 * C_EMB, C_EMB);

    // Causal attention
    flash_attn<<<dim3(T_SEQ / 64, NH, BATCH), 128, FLASH_SMEM_BYTES>>>(qkv, att);

    // Output projection: 8192 x 768 x 768
    sgemm_nt_bias<<<dim3(C_EMB / 128, M_ROWS / 128), 256>>>(
        att, w2, b2, out, M_ROWS, C_EMB, C_EMB);
}